// round 3
// baseline (speedup 1.0000x reference)
#include <cuda_runtime.h>
#include <cstdint>

// CTC forward, scaled linear-domain forward algorithm in FP64.
// One CTA per batch element, one thread per extended-label state (L=801).
// Global power-of-2 rescale every 64 steps (C = 2^(K - e_blockmax), exact),
// integer exponent accumulator Z removes the scale at the end.
// Single __syncthreads per step; prow (f32 ex2 -> f64) double-buffered.

#define T_DIM 2000
#define V_DIM 256
#define S_DIM 400
#define L_DIM 801           // 2*S+1
#define NTHREADS 832        // 26 warps: 801 states + reducer slack
#define KEXP 850            // target exponent of block max at rescale
#define RMASK 63            // rescale every 64 steps

__device__ float g_partial[64];

__device__ __forceinline__ float ex2f(float x) {
    float y; asm("ex2.approx.f32 %0, %1;" : "=f"(y) : "f"(x)); return y;
}
__device__ __forceinline__ float lg2f(float x) {
    float y; asm("lg2.approx.f32 %0, %1;" : "=f"(y) : "f"(x)); return y;
}

__global__ __launch_bounds__(NTHREADS, 1)
void ctc_kernel(const float* __restrict__ logp,
                const int*   __restrict__ targets,
                const int*   __restrict__ ilen,
                const int*   __restrict__ tlen)
{
    __shared__ double alpha[2][L_DIM + 2];   // +2 front guard (always 0)
    __shared__ double prow[2][V_DIM];        // probabilities, widened to f64
    __shared__ int    wmax[32];
    __shared__ double Cslot;                 // rescale factor (exact power of 2)

    const int b   = blockIdx.x;
    const int tid = threadIdx.x;
    const float* lpb = logp + (size_t)b * T_DIM * V_DIM;
    const int il  = ilen[b];
    const int tl  = tlen[b];
    const int s   = tid;
    const int end = 2 * tl;
    const bool isState = (s < L_DIM) && (s <= end);

    // extended label + skip-mask
    int  lbl  = 1;               // BLANK
    bool skip = false;
    if (s < L_DIM && (s & 1)) {
        lbl = targets[b * S_DIM + (s >> 1)];
        if (s >= 3) skip = (lbl != targets[b * S_DIM + ((s - 2) >> 1)]);
    }
    const float l2e = 1.4426950408889634f;

    // zero both alpha buffers (incl. guard cells)
    for (int i = tid; i < 2 * (L_DIM + 2); i += NTHREADS)
        ((double*)alpha)[i] = 0.0;

    // probability rows 0 and 1 (il >= 2 in this dataset)
    if (tid < V_DIM) {
        prow[0][tid] = (double)ex2f(lpb[0 * V_DIM + tid] * l2e);
        prow[1][tid] = (double)ex2f(lpb[1 * V_DIM + tid] * l2e);
    }
    __syncthreads();

    // ---- t = 0 init: alpha0 = p0 * 2^K ----
    double* a0buf = &alpha[0][2];
    const double K2 = __longlong_as_double(((long long)(KEXP + 1023)) << 52);
    double myv = 0.0;
    if (tid == 0) { myv = prow[0][1]   * K2; a0buf[0] = myv; }
    if (tid == 1) { myv = prow[0][lbl] * K2; a0buf[1] = myv; }
    {
        unsigned mm = __reduce_max_sync(0xffffffffu, (unsigned)__double2hiint(myv));
        if ((tid & 31) == 0) wmax[tid >> 5] = (int)mm;
    }
    __syncthreads();

    int Z = KEXP;               // meaningful in thread 800 only
    if (tid >= 800) {           // warp 25 is the reducer
        int la = tid - 800;
        unsigned v = (la < 26) ? (unsigned)wmax[la] : 0u;
        unsigned m = __reduce_max_sync(0xffffffffu, v);
        if (tid == 800) {
            int e  = (int)(m >> 20) - 1023;
            int sh = KEXP - e;
            sh = max(-1000, min(1000, sh));
            Cslot = __longlong_as_double(((long long)(sh + 1023)) << 52);
            if (il > 1) Z += sh;
        }
    }
    // logp prefetch queue, depth 2
    float lp0 = 0.0f, lp1 = 0.0f;
    if (tid < V_DIM) {
        if (il > 2) lp0 = lpb[2 * V_DIM + tid];
        if (il > 3) lp1 = lpb[3 * V_DIM + tid];
    }
    __syncthreads();

    // ---- main recursion t = 1 .. il-1 ----
    for (int t = 1; t < il; ++t) {
        double* prev = &alpha[(t + 1) & 1][2];
        double* cur  = &alpha[t & 1][2];

        double nv = 0.0;
        if (isState) {
            double a  = prev[s];
            double a1 = prev[s - 1];
            double a2 = skip ? prev[s - 2] : 0.0;
            double pm = prow[t & 1][lbl];
            if ((t & RMASK) == 1) pm *= Cslot;   // apply last rescale factor
            nv = (a + a1 + a2) * pm;
            cur[s] = nv;
        }
        if ((t & RMASK) == 0) {                  // measure block max this step
            unsigned mm = __reduce_max_sync(0xffffffffu,
                                            (unsigned)__double2hiint(nv));
            if ((tid & 31) == 0) wmax[tid >> 5] = (int)mm;
        }
        // converters: prob row t+1 (other parity buffer -> no extra barrier)
        if (tid < V_DIM) {
            if (t + 1 < il)
                prow[(t + 1) & 1][tid] = (double)ex2f(lp0 * l2e);
            lp0 = lp1;
            if (t + 3 < il)
                lp1 = lpb[(size_t)(t + 3) * V_DIM + tid];
        }
        __syncthreads();

        if ((t & RMASK) == 0) {                  // reducer computes C for t+1
            if (tid >= 800) {
                int la = tid - 800;
                unsigned v = (la < 26) ? (unsigned)wmax[la] : 0u;
                unsigned m = __reduce_max_sync(0xffffffffu, v);
                if (tid == 800) {
                    int e  = (int)(m >> 20) - 1023;
                    int sh = KEXP - e;
                    sh = max(-1000, min(1000, sh));
                    Cslot = __longlong_as_double(((long long)(sh + 1023)) << 52);
                    if (t + 1 < il) Z += sh;
                }
            }
            __syncthreads();
        }
    }

    // ---- epilogue (thread 800 holds Z) ----
    if (tid == 800) {
        double* fin = &alpha[(il - 1) & 1][2];
        double ssum = fin[end] + fin[end - 1];
        float loss;
        if (ssum <= 0.0) {
            loss = 0.0f;    // total underflow == infeasible -> reference gives 0
        } else {
            long long bits = __double_as_longlong(ssum);
            int e2 = (int)((unsigned long long)bits >> 52) - 1023;
            double mant = __longlong_as_double((bits & 0x000FFFFFFFFFFFFFLL)
                                               | 0x3FF0000000000000LL);
            double ll = 0.6931471805599453 *
                        ((double)e2 + (double)lg2f((float)mant) - (double)Z);
            loss = (float)(-ll);
            if (!(loss < 1e29f)) loss = 0.0f;
        }
        g_partial[b] = loss / (float)tl;
    }
}

__global__ void reduce_kernel(float* out, int B)
{
    float v = 0.0f;
    for (int i = threadIdx.x; i < B; i += 32) v += g_partial[i];
    #pragma unroll
    for (int off = 16; off; off >>= 1)
        v += __shfl_xor_sync(0xffffffffu, v, off);
    if (threadIdx.x == 0) out[0] = v / (float)B;
}

extern "C" void kernel_launch(void* const* d_in, const int* in_sizes, int n_in,
                              void* d_out, int out_size)
{
    const float* logp    = (const float*)d_in[0];
    const int*   targets = (const int*)d_in[1];
    const int*   il      = (const int*)d_in[2];
    const int*   tl      = (const int*)d_in[3];
    const int B = in_sizes[2];

    ctc_kernel<<<B, NTHREADS>>>(logp, targets, il, tl);
    reduce_kernel<<<1, 32>>>((float*)d_out, B);
}